// round 2
// baseline (speedup 1.0000x reference)
#include <cuda_runtime.h>

namespace {
constexpr int  Bc   = 8;
constexpr int  CIN  = 16;
constexpr int  COUT = 16;
constexpr int  KS   = 4;
constexpr long long NN = 524288;   // N
constexpr int  NQ   = 131072;      // N/4 quads (2^17)
constexpr int  THREADS = 128;
}

// Packed fp32x2 FMA / MUL (PTX-only; ptxas never auto-fuses to FFMA2)
__device__ __forceinline__ unsigned long long fma2(unsigned long long a,
                                                   unsigned long long b,
                                                   unsigned long long c) {
    unsigned long long d;
    asm("fma.rn.f32x2 %0, %1, %2, %3;" : "=l"(d) : "l"(a), "l"(b), "l"(c));
    return d;
}
__device__ __forceinline__ unsigned long long mul2(unsigned long long a,
                                                   unsigned long long b) {
    unsigned long long d;
    asm("mul.rn.f32x2 %0, %1, %2;" : "=l"(d) : "l"(a), "l"(b));
    return d;
}

// Key change vs R1: x is STREAMED (read once per channel, released), all 16
// output accumulators live across the pass. Register cap via launch_bounds
// forces ptxas to pipeline loads instead of hoisting everything (R1: 255 regs,
// 12% occupancy, latency-bound at 364us).
__global__ __launch_bounds__(THREADS, 4)
void tconv_f32x2_kernel(const float* __restrict__ inp,   // [B, CIN, N]
                        const float* __restrict__ wgt,   // [COUT, KS, CIN]
                        const float* __restrict__ att,   // [B, KS, N]
                        float* __restrict__ out)         // [B, COUT, N]
{
    // Weights duplicated into (w,w) u64 pairs in SMEM, layout [k][o][c]:
    // inner-loop reads are warp-uniform -> broadcast LDS.64, conflict-free.
    __shared__ unsigned long long wdup[KS * COUT * CIN];
    const int tid = threadIdx.x;
    #pragma unroll
    for (int i = tid; i < KS * COUT * CIN; i += THREADS) {
        int k = i >> 8, o = (i >> 4) & 15, c = i & 15;
        unsigned int bits = __float_as_uint(wgt[(o * KS + k) * CIN + c]);
        wdup[i] = ((unsigned long long)bits << 32) | bits;
    }
    __syncthreads();

    const int idx = blockIdx.x * THREADS + tid;     // one thread = one (b, n-quad)
    const int b   = idx >> 17;                      // NQ = 2^17
    const long long n4 = (long long)(idx & (NQ - 1)) << 2;

    const float* xb = inp + (long long)b * CIN * NN + n4;
    const float* sb = att + (long long)b * KS  * NN + n4;
    float*       ob = out + (long long)b * COUT * NN + n4;

    // Score taps: 4 x LDG.128, stay resident (16 regs).
    unsigned long long slo[KS], shi[KS];
    #pragma unroll
    for (int k = 0; k < KS; k++) {
        ulonglong2 v = *reinterpret_cast<const ulonglong2*>(sb + (long long)k * NN);
        slo[k] = v.x; shi[k] = v.y;
    }

    // All 16 output accumulators (64 regs).
    unsigned long long alo[COUT], ahi[COUT];
    #pragma unroll
    for (int o = 0; o < COUT; o++) { alo[o] = 0ull; ahi[o] = 0ull; }

    // Stream input channels: one LDG.128 in, 128 fma2 out, x released.
    #pragma unroll
    for (int c = 0; c < CIN; c++) {
        ulonglong2 xv = *reinterpret_cast<const ulonglong2*>(xb + (long long)c * NN);
        #pragma unroll
        for (int k = 0; k < KS; k++) {
            unsigned long long zl = mul2(xv.x, slo[k]);
            unsigned long long zh = mul2(xv.y, shi[k]);
            const unsigned long long* wrow = &wdup[k * (COUT * CIN) + c];
            #pragma unroll
            for (int o = 0; o < COUT; o++) {
                unsigned long long w = wrow[o * CIN];   // broadcast LDS.64
                alo[o] = fma2(w, zl, alo[o]);
                ahi[o] = fma2(w, zh, ahi[o]);
            }
        }
    }

    #pragma unroll
    for (int o = 0; o < COUT; o++) {
        ulonglong2 r; r.x = alo[o]; r.y = ahi[o];
        *reinterpret_cast<ulonglong2*>(ob + (long long)o * NN) = r;
    }
}

extern "C" void kernel_launch(void* const* d_in, const int* in_sizes, int n_in,
                              void* d_out, int out_size)
{
    const float* inp = (const float*)d_in[0];   // input  [8,16,524288]
    const float* wgt = (const float*)d_in[1];   // weight [16,4,16]
    const float* att = (const float*)d_in[2];   // attention_score [8,4,524288]
    float* out = (float*)d_out;                 // [8,16,524288]

    const int total_threads = Bc * NQ;          // 1,048,576
    tconv_f32x2_kernel<<<total_threads / THREADS, THREADS>>>(inp, wgt, att, out);
}

// round 3
// speedup vs baseline: 2.6031x; 2.6031x over previous
#include <cuda_runtime.h>

namespace {
constexpr int  Bc   = 8;
constexpr int  CIN  = 16;
constexpr int  COUT = 16;
constexpr int  KS   = 4;
constexpr long long NN = 524288;   // N
constexpr int  NQ   = 131072;      // N/4 quads (2^17)
constexpr int  THREADS = 128;
}

// Packed fp32x2 FMA / MUL (PTX-only; ptxas never auto-fuses to FFMA2)
__device__ __forceinline__ unsigned long long fma2(unsigned long long a,
                                                   unsigned long long b,
                                                   unsigned long long c) {
    unsigned long long d;
    asm("fma.rn.f32x2 %0, %1, %2, %3;" : "=l"(d) : "l"(a), "l"(b), "l"(c));
    return d;
}
__device__ __forceinline__ unsigned long long mul2(unsigned long long a,
                                                   unsigned long long b) {
    unsigned long long d;
    asm("mul.rn.f32x2 %0, %1, %2;" : "=l"(d) : "l"(a), "l"(b));
    return d;
}

// R3: c-loop NOT unrolled (stops ptxas hoisting all x loads -> R2's spills),
// one-deep manual x prefetch, weights in SMEM as [c][o][k] duplicated u64
// pairs so each (c,o) needs 2 broadcast LDS.128 instead of 4 LDS.64.
__global__ __launch_bounds__(THREADS, 4)
void tconv_f32x2_kernel(const float* __restrict__ inp,   // [B, CIN, N]
                        const float* __restrict__ wgt,   // [COUT, KS, CIN]
                        const float* __restrict__ att,   // [B, KS, N]
                        float* __restrict__ out)         // [B, COUT, N]
{
    // wdup[c][o][k]: k contiguous -> ld.shared.v2.u64 pairs, warp-uniform
    // (broadcast, conflict-free).
    __shared__ unsigned long long wdup[CIN * COUT * KS];
    const int tid = threadIdx.x;
    #pragma unroll
    for (int i = tid; i < CIN * COUT * KS; i += THREADS) {
        int c = i >> 6, o = (i >> 2) & 15, k = i & 3;
        unsigned int bits = __float_as_uint(wgt[(o * KS + k) * CIN + c]);
        wdup[i] = ((unsigned long long)bits << 32) | bits;
    }
    __syncthreads();

    const int idx = blockIdx.x * THREADS + tid;     // one thread = one (b, n-quad)
    const int b   = idx >> 17;                      // NQ = 2^17
    const long long n4 = (long long)(idx & (NQ - 1)) << 2;

    const float* xb = inp + (long long)b * CIN * NN + n4;
    const float* sb = att + (long long)b * KS  * NN + n4;
    float*       ob = out + (long long)b * COUT * NN + n4;

    // Score taps resident (16 regs).
    unsigned long long slo[KS], shi[KS];
    #pragma unroll
    for (int k = 0; k < KS; k++) {
        ulonglong2 v = *reinterpret_cast<const ulonglong2*>(sb + (long long)k * NN);
        slo[k] = v.x; shi[k] = v.y;
    }

    // 16 output accumulators (64 regs).
    unsigned long long alo[COUT], ahi[COUT];
    #pragma unroll
    for (int o = 0; o < COUT; o++) { alo[o] = 0ull; ahi[o] = 0ull; }

    // Prefetch channel 0.
    ulonglong2 xnext = *reinterpret_cast<const ulonglong2*>(xb);

    #pragma unroll 1
    for (int c = 0; c < CIN; c++) {
        ulonglong2 xv = xnext;
        // Branchless clamped prefetch of next channel (c=15 reloads itself; harmless).
        int cn = c + 1 < CIN ? c + 1 : CIN - 1;
        xnext = *reinterpret_cast<const ulonglong2*>(xb + (long long)cn * NN);

        // z[k] = x[c] * s[k] for both f32x2 halves (8 mul2, 16 regs).
        unsigned long long zl[KS], zh[KS];
        #pragma unroll
        for (int k = 0; k < KS; k++) {
            zl[k] = mul2(xv.x, slo[k]);
            zh[k] = mul2(xv.y, shi[k]);
        }

        const unsigned long long* wc = &wdup[c * (COUT * KS)];
        #pragma unroll
        for (int o = 0; o < COUT; o++) {
            ulonglong2 w01 = *reinterpret_cast<const ulonglong2*>(wc + o * KS);
            ulonglong2 w23 = *reinterpret_cast<const ulonglong2*>(wc + o * KS + 2);
            alo[o] = fma2(w01.x, zl[0], alo[o]);
            ahi[o] = fma2(w01.x, zh[0], ahi[o]);
            alo[o] = fma2(w01.y, zl[1], alo[o]);
            ahi[o] = fma2(w01.y, zh[1], ahi[o]);
            alo[o] = fma2(w23.x, zl[2], alo[o]);
            ahi[o] = fma2(w23.x, zh[2], ahi[o]);
            alo[o] = fma2(w23.y, zl[3], alo[o]);
            ahi[o] = fma2(w23.y, zh[3], ahi[o]);
        }
    }

    #pragma unroll
    for (int o = 0; o < COUT; o++) {
        ulonglong2 r; r.x = alo[o]; r.y = ahi[o];
        *reinterpret_cast<ulonglong2*>(ob + (long long)o * NN) = r;
    }
}

extern "C" void kernel_launch(void* const* d_in, const int* in_sizes, int n_in,
                              void* d_out, int out_size)
{
    const float* inp = (const float*)d_in[0];   // input  [8,16,524288]
    const float* wgt = (const float*)d_in[1];   // weight [16,4,16]
    const float* att = (const float*)d_in[2];   // attention_score [8,4,524288]
    float* out = (float*)d_out;                 // [8,16,524288]

    const int total_threads = Bc * NQ;          // 1,048,576
    tconv_f32x2_kernel<<<total_threads / THREADS, THREADS>>>(inp, wgt, att, out);
}